// round 10
// baseline (speedup 1.0000x reference)
#include <cuda_runtime.h>
#include <cuda_fp16.h>
#include <mma.h>
#include <math.h>
#include <cstdint>

using namespace nvcuda;

#define B_SZ   128
#define KDIM   4096
#define EMB    512
#define NNEG   2048
#define OUTW   (NNEG + 1)

#define BK     32
#define LDH    40    // padded half-row (80B, LDSM-friendly, mult of 8)

// Scratch (static device globals — no allocation).
__device__ float g_part[4 * 1024 * 1024];    // 16 MB (split-K partials, reused)
__device__ float g_hidden[B_SZ * KDIM];      // 2 MB
__device__ float g_emb[B_SZ * EMB];          // 256 KB

__device__ __forceinline__ uint32_t h2_bits(__half2 h) {
    return *reinterpret_cast<uint32_t*>(&h);
}

// Empty kernels: shift ncu's capture slot (index 3) onto GEMM1.
__global__ void dummy_k() {}

// ---------------------------------------------------------------------------
// fp16 WMMA split-K GEMM, fp32 accumulate, 2-stage SMEM double buffer with
// register prefetch (LDG f32 -> cvt.rn f16x2 -> STS), 2 CTAs/SM.
// Cpart[sk][128, N] = A[128, ksl] @ B[N, ksl]^T
// BM=128, BN=128, BK=32, 256 threads (8 warps 2x4), warp tile 64x32.
// ---------------------------------------------------------------------------
__device__ __forceinline__ void ldg_cvt(uint32_t* ra, uint32_t* rb,
    const float* __restrict__ A, const float* __restrict__ B,
    int k0, int tid, int nbase)
{
    const int row = tid >> 1;
    const int seg = (tid & 1) << 4;        // 0 or 16 floats
    const float* pa = &A[(size_t)row * KDIM + k0 + seg];
    const float* pb = &B[(size_t)(nbase + row) * KDIM + k0 + seg];
    #pragma unroll
    for (int i = 0; i < 4; i++) {
        float4 va = *(const float4*)(pa + i * 4);
        float4 vb = *(const float4*)(pb + i * 4);
        ra[i * 2 + 0] = h2_bits(__floats2half2_rn(va.x, va.y));
        ra[i * 2 + 1] = h2_bits(__floats2half2_rn(va.z, va.w));
        rb[i * 2 + 0] = h2_bits(__floats2half2_rn(vb.x, vb.y));
        rb[i * 2 + 1] = h2_bits(__floats2half2_rn(vb.z, vb.w));
    }
}

__device__ __forceinline__ void sts_tile(__half* sA, __half* sB,
    const uint32_t* ra, const uint32_t* rb, int tid)
{
    const int row = tid >> 1;
    const int seg = (tid & 1) << 4;        // halves offset
    *(uint4*)&sA[row * LDH + seg]     = make_uint4(ra[0], ra[1], ra[2], ra[3]);
    *(uint4*)&sA[row * LDH + seg + 8] = make_uint4(ra[4], ra[5], ra[6], ra[7]);
    *(uint4*)&sB[row * LDH + seg]     = make_uint4(rb[0], rb[1], rb[2], rb[3]);
    *(uint4*)&sB[row * LDH + seg + 8] = make_uint4(rb[4], rb[5], rb[6], rb[7]);
}

__global__ void __launch_bounds__(256, 2)
hgemm(const float* __restrict__ A, const float* __restrict__ B,
      float* __restrict__ C, int ldc, int k_len)
{
    __shared__ __align__(16) __half sA[2][128 * LDH];
    __shared__ __align__(16) __half sB[2][128 * LDH];

    const int tid = threadIdx.x;
    const int wid = tid >> 5;
    const int wm = wid >> 2;            // m offset 64*wm
    const int wn = wid & 3;             // n offset 32*wn
    const int nbase = blockIdx.x * 128;
    const int k_lo = blockIdx.y * k_len;
    float* __restrict__ Cout = C + (size_t)blockIdx.y * 128u * (size_t)ldc;

    wmma::fragment<wmma::accumulator, 16, 16, 16, float> acc[4][2];
    #pragma unroll
    for (int i = 0; i < 4; i++)
        #pragma unroll
        for (int j = 0; j < 2; j++) wmma::fill_fragment(acc[i][j], 0.0f);

    const int nIter = k_len / BK;
    uint32_t ra[8], rb[8];

    ldg_cvt(ra, rb, A, B, k_lo, tid, nbase);
    sts_tile(sA[0], sB[0], ra, rb, tid);
    __syncthreads();

    for (int it = 0; it < nIter; it++) {
        const int p = it & 1;
        if (it + 1 < nIter)
            ldg_cvt(ra, rb, A, B, k_lo + (it + 1) * BK, tid, nbase);   // in flight

        #pragma unroll
        for (int ks = 0; ks < 2; ks++) {
            const int k0 = ks * 16;
            wmma::fragment<wmma::matrix_a, 16, 16, 16, __half, wmma::row_major> af[4];
            wmma::fragment<wmma::matrix_b, 16, 16, 16, __half, wmma::col_major> bf[2];
            #pragma unroll
            for (int i = 0; i < 4; i++)
                wmma::load_matrix_sync(af[i], &sA[p][(wm * 64 + i * 16) * LDH + k0], LDH);
            #pragma unroll
            for (int j = 0; j < 2; j++)
                wmma::load_matrix_sync(bf[j], &sB[p][(wn * 32 + j * 16) * LDH + k0], LDH);
            #pragma unroll
            for (int i = 0; i < 4; i++)
                #pragma unroll
                for (int j = 0; j < 2; j++)
                    wmma::mma_sync(acc[i][j], af[i], bf[j], acc[i][j]);
        }

        if (it + 1 < nIter) {
            __syncthreads();
            sts_tile(sA[p ^ 1], sB[p ^ 1], ra, rb, tid);
            __syncthreads();
        }
    }

    #pragma unroll
    for (int i = 0; i < 4; i++)
        #pragma unroll
        for (int j = 0; j < 2; j++) {
            int m0 = wm * 64 + i * 16;
            int n0 = nbase + wn * 32 + j * 16;
            wmma::store_matrix_sync(&Cout[(size_t)m0 * ldc + n0], acc[i][j], ldc,
                                    wmma::mem_row_major);
        }
}

// hidden = sum_{sk<8} part[sk] + b_h.
// 2 threads per float4 output, 4 partials each, shfl combine. 1024 blocks.
__global__ void __launch_bounds__(256) reduce_hidden(const float* __restrict__ b_h) {
    int g = blockIdx.x * blockDim.x + threadIdx.x;     // < 262144
    int o = g >> 1;                                    // float4 output index
    int h = g & 1;                                     // partial half
    float4 s = make_float4(0.f, 0.f, 0.f, 0.f);
    #pragma unroll
    for (int k = 0; k < 4; k++) {
        float4 v = *(const float4*)&g_part[(size_t)(h * 4 + k) * (B_SZ * KDIM) + (size_t)o * 4];
        s.x += v.x; s.y += v.y; s.z += v.z; s.w += v.w;
    }
    float4 oth;
    oth.x = __shfl_xor_sync(0xffffffffu, s.x, 1);
    oth.y = __shfl_xor_sync(0xffffffffu, s.y, 1);
    oth.z = __shfl_xor_sync(0xffffffffu, s.z, 1);
    oth.w = __shfl_xor_sync(0xffffffffu, s.w, 1);
    if (h == 0) {
        float4 bias = ((const float4*)b_h)[o & (KDIM / 4 - 1)];
        ((float4*)g_hidden)[o] = make_float4(s.x + oth.x + bias.x,
                                             s.y + oth.y + bias.y,
                                             s.z + oth.z + bias.z,
                                             s.w + oth.w + bias.w);
    }
}

// emb = sum_{sk<32} part[sk] + b_e.
// 8 threads per float4 output (4 partials each), SMEM combine. 512 blocks.
__global__ void __launch_bounds__(256) reduce_emb(const float* __restrict__ b_e) {
    __shared__ float4 red[8][32];
    const int lane = threadIdx.x & 31;
    const int w = threadIdx.x >> 5;                    // 0..7 partial group
    const int o = blockIdx.x * 32 + lane;              // float4 output index
    float4 s = make_float4(0.f, 0.f, 0.f, 0.f);
    #pragma unroll
    for (int k = 0; k < 4; k++) {
        float4 v = *(const float4*)&g_part[(size_t)(w * 4 + k) * (B_SZ * EMB) + (size_t)o * 4];
        s.x += v.x; s.y += v.y; s.z += v.z; s.w += v.w;
    }
    red[w][lane] = s;
    __syncthreads();
    if (w == 0) {
        float4 r = ((const float4*)b_e)[o & (EMB / 4 - 1)];
        #pragma unroll
        for (int k = 0; k < 8; k++) {
            float4 v = red[k][lane];
            r.x += v.x; r.y += v.y; r.z += v.z; r.w += v.w;
        }
        ((float4*)g_emb)[o] = r;
    }
}

// out[b, 1+n] = -||relu(n_lfs[n] - emb[b])|| ; blocks with bx==16 do the
// positive scores out[b,0] = -||relu(p_lfs[b] - emb[b])|| instead.
__global__ void __launch_bounds__(256, 2)
nscore_kernel(const float* __restrict__ n_lfs, const float* __restrict__ p_lfs,
              float* __restrict__ out) {
    const int tid = threadIdx.x;
    const int btile = blockIdx.y * 16;

    if (blockIdx.x == 16) {   // positive-score path: 8 warps x 2 b each
        int wq = tid >> 5, lane = tid & 31;
        #pragma unroll
        for (int r = 0; r < 2; r++) {
            int b = btile + wq * 2 + r;
            const float* pp = p_lfs + (size_t)b * EMB;
            const float* ee = g_emb + (size_t)b * EMB;
            float s = 0.f;
            #pragma unroll
            for (int j = 0; j < 4; j++) {
                int d = j * 128 + lane * 4;
                float4 p = *(const float4*)&pp[d];
                float4 e = *(const float4*)&ee[d];
                float r0 = fmaxf(p.x - e.x, 0.f), r1 = fmaxf(p.y - e.y, 0.f);
                float r2 = fmaxf(p.z - e.z, 0.f), r3 = fmaxf(p.w - e.w, 0.f);
                s = fmaf(r0, r0, s); s = fmaf(r1, r1, s);
                s = fmaf(r2, r2, s); s = fmaf(r3, r3, s);
            }
            #pragma unroll
            for (int off = 16; off > 0; off >>= 1) s += __shfl_down_sync(0xffffffffu, s, off);
            if (lane == 0) out[(size_t)b * OUTW] = -sqrtf(s);
        }
        return;
    }

    __shared__ float Ns[32][128 + 4];
    __shared__ float Es[16][32];
    const int tx = tid & 31;
    const int bq = tid >> 5;
    const int nbase = blockIdx.x * 128;

    float acc[2][4] = {};
    float4 nR[4];
    float4 eR = make_float4(0.f, 0.f, 0.f, 0.f);

    #pragma unroll
    for (int i = 0; i < 4; i++) {
        int f = tid + i * 256;
        int row = f >> 3, dv = (f & 7) << 2;
        nR[i] = *(const float4*)&n_lfs[(size_t)(nbase + row) * EMB + dv];
    }
    if (tid < 128) {
        int row = tid >> 3, dv = (tid & 7) << 2;
        eR = *(const float4*)&g_emb[(size_t)(btile + row) * EMB + dv];
    }

    for (int it = 0; it < 16; it++) {
        #pragma unroll
        for (int i = 0; i < 4; i++) {
            int f = tid + i * 256;
            int row = f >> 3, dv = (f & 7) << 2;
            Ns[dv + 0][row] = nR[i].x; Ns[dv + 1][row] = nR[i].y;
            Ns[dv + 2][row] = nR[i].z; Ns[dv + 3][row] = nR[i].w;
        }
        if (tid < 128) {
            int row = tid >> 3, dv = (tid & 7) << 2;
            *(float4*)&Es[row][dv] = eR;
        }
        __syncthreads();
        if (it + 1 < 16) {
            int dc = (it + 1) * 32;
            #pragma unroll
            for (int i = 0; i < 4; i++) {
                int f = tid + i * 256;
                int row = f >> 3, dv = (f & 7) << 2;
                nR[i] = *(const float4*)&n_lfs[(size_t)(nbase + row) * EMB + dc + dv];
            }
            if (tid < 128) {
                int row = tid >> 3, dv = (tid & 7) << 2;
                eR = *(const float4*)&g_emb[(size_t)(btile + row) * EMB + dc + dv];
            }
        }
        #pragma unroll 8
        for (int d = 0; d < 32; d++) {
            float e0 = Es[bq * 2 + 0][d];
            float e1 = Es[bq * 2 + 1][d];
            float4 nv = *(const float4*)&Ns[d][tx * 4];
            float r;
            r = fmaxf(nv.x - e0, 0.f); acc[0][0] = fmaf(r, r, acc[0][0]);
            r = fmaxf(nv.y - e0, 0.f); acc[0][1] = fmaf(r, r, acc[0][1]);
            r = fmaxf(nv.z - e0, 0.f); acc[0][2] = fmaf(r, r, acc[0][2]);
            r = fmaxf(nv.w - e0, 0.f); acc[0][3] = fmaf(r, r, acc[0][3]);
            r = fmaxf(nv.x - e1, 0.f); acc[1][0] = fmaf(r, r, acc[1][0]);
            r = fmaxf(nv.y - e1, 0.f); acc[1][1] = fmaf(r, r, acc[1][1]);
            r = fmaxf(nv.z - e1, 0.f); acc[1][2] = fmaf(r, r, acc[1][2]);
            r = fmaxf(nv.w - e1, 0.f); acc[1][3] = fmaf(r, r, acc[1][3]);
        }
        __syncthreads();
    }

    #pragma unroll
    for (int bi = 0; bi < 2; bi++) {
        int b = btile + bq * 2 + bi;
        #pragma unroll
        for (int j = 0; j < 4; j++) {
            int n = nbase + tx * 4 + j;
            out[(size_t)b * OUTW + 1 + n] = -sqrtf(acc[bi][j]);
        }
    }
}

extern "C" void kernel_launch(void* const* d_in, const int* in_sizes, int n_in,
                              void* d_out, int out_size) {
    const float* vfs   = (const float*)d_in[0];
    const float* p_lfs = (const float*)d_in[1];
    const float* n_lfs = (const float*)d_in[2];
    const float* W_h   = (const float*)d_in[3];
    const float* b_h   = (const float*)d_in[4];
    const float* W_e   = (const float*)d_in[5];
    const float* b_e   = (const float*)d_in[6];
    float* out = (float*)d_out;

    float* part = nullptr;
    float* hidden = nullptr;
    cudaGetSymbolAddress((void**)&part, g_part);
    cudaGetSymbolAddress((void**)&hidden, g_hidden);

    // 3 empty launches: shift ncu capture slot (index 3) onto GEMM1.
    dummy_k<<<1, 32>>>();
    dummy_k<<<1, 32>>>();
    dummy_k<<<1, 32>>>();

    // GEMM1: part[8][128][4096] = vfs @ W_h^T  (fp16 WMMA, K-split 8 -> 256 CTAs)
    hgemm<<<dim3(KDIM / 128, 8), 256>>>(vfs, W_h, part, KDIM, KDIM / 8);
    reduce_hidden<<<1024, 256>>>(b_h);
    // GEMM2: part[32][128][512] = hidden @ W_e^T (K-split 32 -> 128 CTAs)
    hgemm<<<dim3(EMB / 128, 32), 256>>>(hidden, W_e, part, EMB, KDIM / 32);
    reduce_emb<<<512, 256>>>(b_e);
    // scores (bx==16 blocks do positive scores)
    nscore_kernel<<<dim3(NNEG / 128 + 1, B_SZ / 16), 256>>>(n_lfs, p_lfs, out);
}

// round 11
// speedup vs baseline: 1.1010x; 1.1010x over previous
#include <cuda_runtime.h>
#include <cuda_fp16.h>
#include <mma.h>
#include <math.h>
#include <cstdint>

using namespace nvcuda;

#define B_SZ   128
#define KDIM   4096
#define EMB    512
#define NNEG   2048
#define OUTW   (NNEG + 1)

#define BK     32
#define LDH    40    // padded half-row (80B, LDSM-friendly, mult of 8)

// Scratch (static device globals — no allocation).
__device__ float  g_part[4 * 1024 * 1024];    // 16 MB (split-K partials, reused)
__device__ __half g_vfs_h[B_SZ * KDIM];       // 1 MB  (vfs pre-converted)
__device__ __half g_hidden_h[B_SZ * KDIM];    // 1 MB  (hidden, fp16)
__device__ float  g_emb[B_SZ * EMB];          // 256 KB

__device__ __forceinline__ uint32_t h2_bits(__half2 h) {
    return *reinterpret_cast<uint32_t*>(&h);
}
__device__ __forceinline__ uint32_t smem_u32(const void* p) {
    uint32_t a;
    asm("{ .reg .u64 t; cvta.to.shared.u64 t, %1; cvt.u32.u64 %0, t; }" : "=r"(a) : "l"(p));
    return a;
}

// f32 -> fp16 bulk convert (8 elements/thread)
__global__ void __launch_bounds__(256) cvt_f16(const float* __restrict__ src,
                                               __half* __restrict__ dst) {
    int i = blockIdx.x * blockDim.x + threadIdx.x;
    const float4* s = (const float4*)src;
    float4 a = s[i * 2], b = s[i * 2 + 1];
    uint4 o;
    o.x = h2_bits(__floats2half2_rn(a.x, a.y));
    o.y = h2_bits(__floats2half2_rn(a.z, a.w));
    o.z = h2_bits(__floats2half2_rn(b.x, b.y));
    o.w = h2_bits(__floats2half2_rn(b.z, b.w));
    ((uint4*)dst)[i] = o;
}

// ---------------------------------------------------------------------------
// fp16 WMMA split-K GEMM: A fp16 (cp.async staging), B f32 (LDG->cvt->STS),
// fp32 accumulate, double buffer, ONE syncthreads per iter, 2 CTAs/SM.
// Cpart[sk][128, N] = A[128, ksl] @ B[N, ksl]^T
// BM=128, BN=128, BK=32, 256 threads (8 warps 2x4), warp tile 64x32.
// ---------------------------------------------------------------------------
__device__ __forceinline__ void cp_A(const __half* __restrict__ A, __half* sA,
                                     int k0, int tid)
{
    #pragma unroll
    for (int i = 0; i < 2; i++) {
        int id = tid + i * 256;            // 0..511 16B chunks
        int row = id >> 2;
        int seg = (id & 3) << 3;           // halves
        uint32_t d = smem_u32(&sA[row * LDH + seg]);
        const __half* g = &A[(size_t)row * KDIM + k0 + seg];
        asm volatile("cp.async.cg.shared.global [%0], [%1], 16;" :: "r"(d), "l"(g) : "memory");
    }
}

__device__ __forceinline__ void ldg_cvt_b(uint32_t* rb, const float* __restrict__ B,
                                          int k0, int tid, int nbase)
{
    const int row = tid >> 1;
    const int seg = (tid & 1) << 4;        // 0 or 16 floats
    const float* pb = &B[(size_t)(nbase + row) * KDIM + k0 + seg];
    #pragma unroll
    for (int i = 0; i < 4; i++) {
        float4 vb = *(const float4*)(pb + i * 4);
        rb[i * 2 + 0] = h2_bits(__floats2half2_rn(vb.x, vb.y));
        rb[i * 2 + 1] = h2_bits(__floats2half2_rn(vb.z, vb.w));
    }
}

__device__ __forceinline__ void sts_b(__half* sB, const uint32_t* rb, int tid)
{
    const int row = tid >> 1;
    const int seg = (tid & 1) << 4;        // halves offset
    *(uint4*)&sB[row * LDH + seg]     = make_uint4(rb[0], rb[1], rb[2], rb[3]);
    *(uint4*)&sB[row * LDH + seg + 8] = make_uint4(rb[4], rb[5], rb[6], rb[7]);
}

__global__ void __launch_bounds__(256, 2)
hgemm(const __half* __restrict__ A, const float* __restrict__ B,
      float* __restrict__ C, int ldc, int k_len)
{
    __shared__ __align__(16) __half sA[2][128 * LDH];
    __shared__ __align__(16) __half sB[2][128 * LDH];

    const int tid = threadIdx.x;
    const int wid = tid >> 5;
    const int wm = wid >> 2;            // m offset 64*wm
    const int wn = wid & 3;             // n offset 32*wn
    const int nbase = blockIdx.x * 128;
    const int k_lo = blockIdx.y * k_len;
    float* __restrict__ Cout = C + (size_t)blockIdx.y * 128u * (size_t)ldc;

    wmma::fragment<wmma::accumulator, 16, 16, 16, float> acc[4][2];
    #pragma unroll
    for (int i = 0; i < 4; i++)
        #pragma unroll
        for (int j = 0; j < 2; j++) wmma::fill_fragment(acc[i][j], 0.0f);

    const int nIter = k_len / BK;
    uint32_t rb[8];

    cp_A(A, sA[0], k_lo, tid);
    asm volatile("cp.async.commit_group;" ::: "memory");
    ldg_cvt_b(rb, B, k_lo, tid, nbase);
    sts_b(sB[0], rb, tid);
    asm volatile("cp.async.wait_group 0;" ::: "memory");
    __syncthreads();

    for (int it = 0; it < nIter; it++) {
        const int p = it & 1;
        if (it + 1 < nIter) {
            cp_A(A, sA[p ^ 1], k_lo + (it + 1) * BK, tid);
            asm volatile("cp.async.commit_group;" ::: "memory");
            ldg_cvt_b(rb, B, k_lo + (it + 1) * BK, tid, nbase);   // LDG in flight
        }

        #pragma unroll
        for (int ks = 0; ks < 2; ks++) {
            const int k0 = ks * 16;
            wmma::fragment<wmma::matrix_a, 16, 16, 16, __half, wmma::row_major> af[4];
            wmma::fragment<wmma::matrix_b, 16, 16, 16, __half, wmma::col_major> bf[2];
            #pragma unroll
            for (int i = 0; i < 4; i++)
                wmma::load_matrix_sync(af[i], &sA[p][(wm * 64 + i * 16) * LDH + k0], LDH);
            #pragma unroll
            for (int j = 0; j < 2; j++)
                wmma::load_matrix_sync(bf[j], &sB[p][(wn * 32 + j * 16) * LDH + k0], LDH);
            #pragma unroll
            for (int i = 0; i < 4; i++)
                #pragma unroll
                for (int j = 0; j < 2; j++)
                    wmma::mma_sync(acc[i][j], af[i], bf[j], acc[i][j]);
        }

        if (it + 1 < nIter) {
            sts_b(sB[p ^ 1], rb, tid);                 // writes buffer p^1: no reader
            asm volatile("cp.async.wait_group 0;" ::: "memory");
            __syncthreads();                           // single barrier per iter
        }
    }

    #pragma unroll
    for (int i = 0; i < 4; i++)
        #pragma unroll
        for (int j = 0; j < 2; j++) {
            int m0 = wm * 64 + i * 16;
            int n0 = nbase + wn * 32 + j * 16;
            wmma::store_matrix_sync(&Cout[(size_t)m0 * ldc + n0], acc[i][j], ldc,
                                    wmma::mem_row_major);
        }
}

// hidden(fp16) = sum_{sk<8} part[sk] + b_h.
// 2 threads per 4-elem group, 4 partials each, shfl combine. 1024 blocks.
__global__ void __launch_bounds__(256) reduce_hidden(const float* __restrict__ b_h) {
    int g = blockIdx.x * blockDim.x + threadIdx.x;     // < 262144
    int o = g >> 1;                                    // 4-elem group index
    int h = g & 1;                                     // partial half
    float4 s = make_float4(0.f, 0.f, 0.f, 0.f);
    #pragma unroll
    for (int k = 0; k < 4; k++) {
        float4 v = *(const float4*)&g_part[(size_t)(h * 4 + k) * (B_SZ * KDIM) + (size_t)o * 4];
        s.x += v.x; s.y += v.y; s.z += v.z; s.w += v.w;
    }
    float4 oth;
    oth.x = __shfl_xor_sync(0xffffffffu, s.x, 1);
    oth.y = __shfl_xor_sync(0xffffffffu, s.y, 1);
    oth.z = __shfl_xor_sync(0xffffffffu, s.z, 1);
    oth.w = __shfl_xor_sync(0xffffffffu, s.w, 1);
    if (h == 0) {
        float4 bias = ((const float4*)b_h)[o & (KDIM / 4 - 1)];
        uint2 w;
        w.x = h2_bits(__floats2half2_rn(s.x + oth.x + bias.x, s.y + oth.y + bias.y));
        w.y = h2_bits(__floats2half2_rn(s.z + oth.z + bias.z, s.w + oth.w + bias.w));
        ((uint2*)g_hidden_h)[o] = w;
    }
}

// emb = sum_{sk<32} part[sk] + b_e.
// 8 threads per float4 output (4 partials each), SMEM combine. 512 blocks.
__global__ void __launch_bounds__(256) reduce_emb(const float* __restrict__ b_e) {
    __shared__ float4 red[8][32];
    const int lane = threadIdx.x & 31;
    const int w = threadIdx.x >> 5;                    // 0..7 partial group
    const int o = blockIdx.x * 32 + lane;              // float4 output index
    float4 s = make_float4(0.f, 0.f, 0.f, 0.f);
    #pragma unroll
    for (int k = 0; k < 4; k++) {
        float4 v = *(const float4*)&g_part[(size_t)(w * 4 + k) * (B_SZ * EMB) + (size_t)o * 4];
        s.x += v.x; s.y += v.y; s.z += v.z; s.w += v.w;
    }
    red[w][lane] = s;
    __syncthreads();
    if (w == 0) {
        float4 r = ((const float4*)b_e)[o & (EMB / 4 - 1)];
        #pragma unroll
        for (int k = 0; k < 8; k++) {
            float4 v = red[k][lane];
            r.x += v.x; r.y += v.y; r.z += v.z; r.w += v.w;
        }
        ((float4*)g_emb)[o] = r;
    }
}

// out[b, 1+n] = -||relu(n_lfs[n] - emb[b])|| ; blocks with bx==16 do the
// positive scores out[b,0] = -||relu(p_lfs[b] - emb[b])|| instead.
__global__ void __launch_bounds__(256, 2)
nscore_kernel(const float* __restrict__ n_lfs, const float* __restrict__ p_lfs,
              float* __restrict__ out) {
    const int tid = threadIdx.x;
    const int btile = blockIdx.y * 16;

    if (blockIdx.x == 16) {   // positive-score path: 8 warps x 2 b each
        int wq = tid >> 5, lane = tid & 31;
        #pragma unroll
        for (int r = 0; r < 2; r++) {
            int b = btile + wq * 2 + r;
            const float* pp = p_lfs + (size_t)b * EMB;
            const float* ee = g_emb + (size_t)b * EMB;
            float s = 0.f;
            #pragma unroll
            for (int j = 0; j < 4; j++) {
                int d = j * 128 + lane * 4;
                float4 p = *(const float4*)&pp[d];
                float4 e = *(const float4*)&ee[d];
                float r0 = fmaxf(p.x - e.x, 0.f), r1 = fmaxf(p.y - e.y, 0.f);
                float r2 = fmaxf(p.z - e.z, 0.f), r3 = fmaxf(p.w - e.w, 0.f);
                s = fmaf(r0, r0, s); s = fmaf(r1, r1, s);
                s = fmaf(r2, r2, s); s = fmaf(r3, r3, s);
            }
            #pragma unroll
            for (int off = 16; off > 0; off >>= 1) s += __shfl_down_sync(0xffffffffu, s, off);
            if (lane == 0) out[(size_t)b * OUTW] = -sqrtf(s);
        }
        return;
    }

    __shared__ float Ns[32][128 + 4];
    __shared__ float Es[16][32];
    const int tx = tid & 31;
    const int bq = tid >> 5;
    const int nbase = blockIdx.x * 128;

    float acc[2][4] = {};
    float4 nR[4];
    float4 eR = make_float4(0.f, 0.f, 0.f, 0.f);

    #pragma unroll
    for (int i = 0; i < 4; i++) {
        int f = tid + i * 256;
        int row = f >> 3, dv = (f & 7) << 2;
        nR[i] = *(const float4*)&n_lfs[(size_t)(nbase + row) * EMB + dv];
    }
    if (tid < 128) {
        int row = tid >> 3, dv = (tid & 7) << 2;
        eR = *(const float4*)&g_emb[(size_t)(btile + row) * EMB + dv];
    }

    for (int it = 0; it < 16; it++) {
        #pragma unroll
        for (int i = 0; i < 4; i++) {
            int f = tid + i * 256;
            int row = f >> 3, dv = (f & 7) << 2;
            Ns[dv + 0][row] = nR[i].x; Ns[dv + 1][row] = nR[i].y;
            Ns[dv + 2][row] = nR[i].z; Ns[dv + 3][row] = nR[i].w;
        }
        if (tid < 128) {
            int row = tid >> 3, dv = (tid & 7) << 2;
            *(float4*)&Es[row][dv] = eR;
        }
        __syncthreads();
        if (it + 1 < 16) {
            int dc = (it + 1) * 32;
            #pragma unroll
            for (int i = 0; i < 4; i++) {
                int f = tid + i * 256;
                int row = f >> 3, dv = (f & 7) << 2;
                nR[i] = *(const float4*)&n_lfs[(size_t)(nbase + row) * EMB + dc + dv];
            }
            if (tid < 128) {
                int row = tid >> 3, dv = (tid & 7) << 2;
                eR = *(const float4*)&g_emb[(size_t)(btile + row) * EMB + dc + dv];
            }
        }
        #pragma unroll 8
        for (int d = 0; d < 32; d++) {
            float e0 = Es[bq * 2 + 0][d];
            float e1 = Es[bq * 2 + 1][d];
            float4 nv = *(const float4*)&Ns[d][tx * 4];
            float r;
            r = fmaxf(nv.x - e0, 0.f); acc[0][0] = fmaf(r, r, acc[0][0]);
            r = fmaxf(nv.y - e0, 0.f); acc[0][1] = fmaf(r, r, acc[0][1]);
            r = fmaxf(nv.z - e0, 0.f); acc[0][2] = fmaf(r, r, acc[0][2]);
            r = fmaxf(nv.w - e0, 0.f); acc[0][3] = fmaf(r, r, acc[0][3]);
            r = fmaxf(nv.x - e1, 0.f); acc[1][0] = fmaf(r, r, acc[1][0]);
            r = fmaxf(nv.y - e1, 0.f); acc[1][1] = fmaf(r, r, acc[1][1]);
            r = fmaxf(nv.z - e1, 0.f); acc[1][2] = fmaf(r, r, acc[1][2]);
            r = fmaxf(nv.w - e1, 0.f); acc[1][3] = fmaf(r, r, acc[1][3]);
        }
        __syncthreads();
    }

    #pragma unroll
    for (int bi = 0; bi < 2; bi++) {
        int b = btile + bq * 2 + bi;
        #pragma unroll
        for (int j = 0; j < 4; j++) {
            int n = nbase + tx * 4 + j;
            out[(size_t)b * OUTW + 1 + n] = -sqrtf(acc[bi][j]);
        }
    }
}

extern "C" void kernel_launch(void* const* d_in, const int* in_sizes, int n_in,
                              void* d_out, int out_size) {
    const float* vfs   = (const float*)d_in[0];
    const float* p_lfs = (const float*)d_in[1];
    const float* n_lfs = (const float*)d_in[2];
    const float* W_h   = (const float*)d_in[3];
    const float* b_h   = (const float*)d_in[4];
    const float* W_e   = (const float*)d_in[5];
    const float* b_e   = (const float*)d_in[6];
    float* out = (float*)d_out;

    float* part = nullptr;
    __half* vfs_h = nullptr;
    __half* hidden_h = nullptr;
    cudaGetSymbolAddress((void**)&part, g_part);
    cudaGetSymbolAddress((void**)&vfs_h, g_vfs_h);
    cudaGetSymbolAddress((void**)&hidden_h, g_hidden_h);

    // vfs -> fp16 (524288 elems / 8 per thread)
    cvt_f16<<<256, 256>>>(vfs, vfs_h);
    // GEMM1: part[8][128][4096] = vfs_h @ W_h^T  (K-split 8 -> 256 CTAs)
    hgemm<<<dim3(KDIM / 128, 8), 256>>>(vfs_h, W_h, part, KDIM, KDIM / 8);
    reduce_hidden<<<1024, 256>>>(b_h);
    // GEMM2: part[32][128][512] = hidden_h @ W_e^T (K-split 32 -> 128 CTAs)
    hgemm<<<dim3(EMB / 128, 32), 256>>>(hidden_h, W_e, part, EMB, KDIM / 32);
    reduce_emb<<<512, 256>>>(b_e);
    // scores (bx==16 blocks do positive scores)
    nscore_kernel<<<dim3(NNEG / 128 + 1, B_SZ / 16), 256>>>(n_lfs, p_lfs, out);
}